// round 15
// baseline (speedup 1.0000x reference)
#include <cuda_runtime.h>
#include <cuda_bf16.h>
#include <cstdint>

// Problem dims (fixed by dataset)
#define BB 4
#define TT_ 512
#define UU 128
#define DD 512
#define VV 512
#define MS (BB * TT_)    // 2048 speech rows
#define MT (BB * UU)     // 512 text rows
#define MA (MS + MT)     // 2560 combined A rows

// Scratch
__device__ float g_sp[MS * VV];   // speech @ W^T          (4 MB)
__device__ float g_tp[MT * VV];   // text @ W^T + bias     (1 MB)
__device__ __align__(16) __nv_bfloat16 g_Ahi[MA * DD];
__device__ __align__(16) __nv_bfloat16 g_Alo[MA * DD];
__device__ __align__(16) __nv_bfloat16 g_Whi[VV * DD];
__device__ __align__(16) __nv_bfloat16 g_Wlo[VV * DD];

__device__ __forceinline__ uint32_t s2u(const void* p) {
    return (uint32_t)__cvta_generic_to_shared(p);
}

#define LDSM4(r0, r1, r2, r3, addr) \
    asm volatile("ldmatrix.sync.aligned.m8n8.x4.shared.b16 {%0,%1,%2,%3}, [%4];" \
                 : "=r"(r0), "=r"(r1), "=r"(r2), "=r"(r3) : "r"(addr))
#define MMA16816(d, a0, a1, a2, a3, b0, b1) \
    asm volatile("mma.sync.aligned.m16n8k16.row.col.f32.bf16.bf16.f32 " \
                 "{%0,%1,%2,%3},{%4,%5,%6,%7},{%8,%9},{%0,%1,%2,%3};" \
                 : "+f"(d[0]), "+f"(d[1]), "+f"(d[2]), "+f"(d[3]) \
                 : "r"(a0), "r"(a1), "r"(a2), "r"(a3), "r"(b0), "r"(b1))
#define CP16(saddr, gptr) \
    asm volatile("cp.async.cg.shared.global [%0], [%1], 16;" \
                 :: "r"(saddr), "l"(gptr))
#define CP_COMMIT() asm volatile("cp.async.commit_group;")
#define CP_WAIT1()  asm volatile("cp.async.wait_group 1;")
#define CP_WAIT0()  asm volatile("cp.async.wait_group 0;")

// ---------------------------------------------------------------------------
// Kernel 0: fp32 -> (bf16 hi, bf16 lo) split of [speech; text] and W.
// 768 blocks x 256 threads x 8 elems = 1,572,864 elements exactly.
// Also writes the float-cast length tail.
// ---------------------------------------------------------------------------
__global__ __launch_bounds__(256)
void convert_kernel(const float* __restrict__ speech,
                    const float* __restrict__ text,
                    const float* __restrict__ Wm,
                    const int* __restrict__ slen,
                    const int* __restrict__ tlen,
                    float* __restrict__ out)
{
    const size_t e = ((size_t)blockIdx.x * 256 + threadIdx.x) * 8;
    const float* src;
    __nv_bfloat16 *dhi, *dlo;
    if (e < (size_t)MS * DD) {
        src = speech + e;               dhi = g_Ahi + e; dlo = g_Alo + e;
    } else if (e < (size_t)MA * DD) {
        src = text + (e - (size_t)MS * DD);
        dhi = g_Ahi + e; dlo = g_Alo + e;
    } else {
        size_t w = e - (size_t)MA * DD;
        src = Wm + w;                   dhi = g_Whi + w; dlo = g_Wlo + w;
    }

    float4 x0 = *(const float4*)src;
    float4 x1 = *(const float4*)(src + 4);
    float xs[8] = {x0.x, x0.y, x0.z, x0.w, x1.x, x1.y, x1.z, x1.w};

    union { __nv_bfloat16 h[8]; uint4 v; } uhi, ulo;
#pragma unroll
    for (int i = 0; i < 8; i++) {
        __nv_bfloat16 h = __float2bfloat16(xs[i]);
        uhi.h[i] = h;
        ulo.h[i] = __float2bfloat16(xs[i] - __bfloat162float(h));
    }
    *(uint4*)dhi = uhi.v;
    *(uint4*)dlo = ulo.v;

    // Length tail: outputs 1 and 2 flattened after logits, as float32.
    if (blockIdx.x == 0 && threadIdx.x < 8) {
        size_t base = (size_t)BB * TT_ * UU * VV;
        int i = threadIdx.x;
        if (i < 4) out[base + i] = (float)slen[i];
        else       out[base + i] = (float)tlen[i - 4];
    }
}

// ---------------------------------------------------------------------------
// Kernel 1: tensor-core split GEMM, 3-stage cp.async pipeline.
// C = Ahi*Whi + Ahi*Wlo + Alo*Whi (mma.sync m16n8k16 bf16, fp32 accum).
// 64x64 tiles, 128 threads = 4 warps in a 2m x 2n grid of m32n32 warp tiles
// (was 8 x m16n32): 8 LDSM4 per 24 HMMA per k16-substep.
// grid 320 (rb>=32 -> text). Stages: {Ahi|Alo|Whi|Wlo} 5120B each.
// ---------------------------------------------------------------------------
__global__ __launch_bounds__(128, 3)
void mma_gemm_kernel(const float* __restrict__ bias)
{
    __shared__ __align__(16) unsigned char smem[3][20480];

    const int t   = blockIdx.x;     // 0..319
    const int tid = threadIdx.x;
    const int rb  = t >> 3;         // 0..39 (combined row-block)
    const int v0  = (t & 7) * 64;
    const bool is_text = (rb >= 32);
    const int m0 = rb * 64;
    float* C = is_text ? g_tp + (size_t)(rb - 32) * 64 * VV
                       : g_sp + (size_t)rb * 64 * VV;

    // gmem->smem loaders: row ar (0..63), two 16B segments per thread
    const int ar = tid >> 1;                  // 0..63
    const int ac = (tid & 1) * 2;             // segment 0/2 (thread covers ac, ac+1)
    const __nv_bfloat16* pAhi = g_Ahi + (size_t)(m0 + ar) * DD + ac * 8;
    const __nv_bfloat16* pAlo = g_Alo + (size_t)(m0 + ar) * DD + ac * 8;
    const __nv_bfloat16* pWhi = g_Whi + (size_t)(v0 + ar) * DD + ac * 8;
    const __nv_bfloat16* pWlo = g_Wlo + (size_t)(v0 + ar) * DD + ac * 8;
    const int soff = ar * 80 + ac * 16;

    // warp tile coords: 2m x 2n grid of m32 x n32 tiles
    const int lane = tid & 31;
    const int wrp  = tid >> 5;      // 0..3
    const int wm   = wrp & 1;       // m32 group
    const int wn   = wrp >> 1;      // n32 group

    // A ldmatrix geometry (x4 = m16 x k16); two m16 strips per warp (im)
    const int aRow  = wm * 32 + (lane & 15);
    const int aByte = ((lane >> 4) & 1) * 16;
    // B LDSM4 packing: (j-pair, k-half) quads; two j-pairs per warp (jp)
    const int bRow4  = wn * 32 + ((lane >> 4) & 1) * 8 + (lane & 7);
    const int bByte4 = ((lane >> 3) & 1) * 16;

    float acc[2][4][4];
#pragma unroll
    for (int im = 0; im < 2; im++)
#pragma unroll
        for (int j = 0; j < 4; j++)
#pragma unroll
            for (int i = 0; i < 4; i++) acc[im][j][i] = 0.f;

    // cp.async issue of chunk kc into stage s (2 x 16B per sub-buffer per thread)
    auto issue = [&](int kc, int s) {
        unsigned char* nb = smem[s];
        const int ko = kc * 32;
        CP16(s2u(nb +         soff), pAhi + ko);
        CP16(s2u(nb +         soff + 16), pAhi + ko + 8);
        CP16(s2u(nb +  5120 + soff), pAlo + ko);
        CP16(s2u(nb +  5120 + soff + 16), pAlo + ko + 8);
        CP16(s2u(nb + 10240 + soff), pWhi + ko);
        CP16(s2u(nb + 10240 + soff + 16), pWhi + ko + 8);
        CP16(s2u(nb + 15360 + soff), pWlo + ko);
        CP16(s2u(nb + 15360 + soff + 16), pWlo + ko + 8);
        CP_COMMIT();
    };

    issue(0, 0);
    issue(1, 1);

    int sbuf = 0;
    for (int kc = 0; kc < 16; kc++) {
        if (kc == 15) { CP_WAIT0(); } else { CP_WAIT1(); }
        __syncthreads();

        if (kc < 14) {
            int ns = sbuf + 2; if (ns >= 3) ns -= 3;
            issue(kc + 2, ns);
        }

        unsigned char* cb = smem[sbuf];
#pragma unroll
        for (int ks = 0; ks < 2; ks++) {
            // A frags: 2 m16 strips x (hi, lo)
            uint32_t ah[2][4], al[2][4];
#pragma unroll
            for (int im = 0; im < 2; im++) {
                uint32_t aAddr = s2u(cb + (aRow + im * 16) * 80 + ks * 32 + aByte);
                LDSM4(ah[im][0], ah[im][1], ah[im][2], ah[im][3], aAddr);
                LDSM4(al[im][0], al[im][1], al[im][2], al[im][3], aAddr + 5120);
            }
            // B frags: 2 j-pairs x (hi, lo)
            uint32_t bh[8], bl[8];
            uint32_t bAddrBase = s2u(cb + 10240 + bRow4 * 80 + ks * 32 + bByte4);
#pragma unroll
            for (int jp = 0; jp < 2; jp++) {
                uint32_t ba = bAddrBase + jp * (16 * 80);
                LDSM4(bh[jp*4+0], bh[jp*4+1], bh[jp*4+2], bh[jp*4+3], ba);
                LDSM4(bl[jp*4+0], bl[jp*4+1], bl[jp*4+2], bl[jp*4+3], ba + 5120);
            }

#pragma unroll
            for (int im = 0; im < 2; im++) {
#pragma unroll
                for (int j = 0; j < 4; j++) {
                    MMA16816(acc[im][j], ah[im][0], ah[im][1], ah[im][2], ah[im][3],
                             bh[j*2], bh[j*2+1]);
                    MMA16816(acc[im][j], ah[im][0], ah[im][1], ah[im][2], ah[im][3],
                             bl[j*2], bl[j*2+1]);
                    MMA16816(acc[im][j], al[im][0], al[im][1], al[im][2], al[im][3],
                             bh[j*2], bh[j*2+1]);
                }
            }
        }
        __syncthreads();
        if (++sbuf == 3) sbuf = 0;
    }

    // Epilogue
    const int ecol0 = wn * 32 + (lane & 3) * 2;
#pragma unroll
    for (int im = 0; im < 2; im++) {
        const int erow = wm * 32 + im * 16 + (lane >> 2);
#pragma unroll
        for (int j = 0; j < 4; j++) {
            const int col = ecol0 + j * 8;
            float b0v = 0.f, b1v = 0.f;
            if (is_text) { b0v = bias[v0 + col]; b1v = bias[v0 + col + 1]; }
            float2 o0 = make_float2(acc[im][j][0] + b0v, acc[im][j][1] + b1v);
            float2 o1 = make_float2(acc[im][j][2] + b0v, acc[im][j][3] + b1v);
            *(float2*)(C + (size_t)erow * VV + v0 + col)       = o0;
            *(float2*)(C + (size_t)(erow + 8) * VV + v0 + col) = o1;
        }
    }
}

// ---------------------------------------------------------------------------
// Kernel 2: broadcast add: out[bt, u, v] = sp[bt, v] + tp[b*U + u, v].
// Exact best-measured config: one block per bt row, 128 threads, plain
// stores. 87.5 us — the HBM write floor.
// ---------------------------------------------------------------------------
__global__ __launch_bounds__(128)
void bcast_add_kernel(float* __restrict__ out)
{
    const int bt  = blockIdx.x;           // 0..2047
    const int b   = bt >> 9;              // bt / T
    const int tid = threadIdx.x;          // 0..127 -> v4 index

    const float4* sp4 = (const float4*)g_sp;
    const float4* tp4 = (const float4*)g_tp;

    float4 s = sp4[(size_t)bt * 128 + tid];

    const float4* tprow = tp4 + (size_t)b * UU * 128 + tid;
    float4* ob = (float4*)out + (size_t)bt * UU * 128 + tid;

#pragma unroll 4
    for (int u = 0; u < UU; u++) {
        float4 t = tprow[(size_t)u * 128];
        float4 r;
        r.x = s.x + t.x;
        r.y = s.y + t.y;
        r.z = s.z + t.z;
        r.w = s.w + t.w;
        ob[(size_t)u * 128] = r;
    }
}

extern "C" void kernel_launch(void* const* d_in, const int* in_sizes, int n_in,
                              void* d_out, int out_size)
{
    const float* speech = (const float*)d_in[0];
    const float* text   = (const float*)d_in[1];
    const float* Wm     = (const float*)d_in[2];
    const float* bias   = (const float*)d_in[3];
    const int*   slen   = (const int*)d_in[4];
    const int*   tlen   = (const int*)d_in[5];

    // Phase 0: fp32 -> bf16 hi/lo split (+ length tail)
    convert_kernel<<<768, 256>>>(speech, text, Wm, slen, tlen, (float*)d_out);

    // Phase 1: tensor-core split GEMM (speech + text w/ bias)
    mma_gemm_kernel<<<320, 128>>>(bias);

    // Phase 2: broadcast add (DRAM-write-bound floor)
    bcast_add_kernel<<<MS, 128>>>((float*)d_out);
}

// round 16
// speedup vs baseline: 1.0738x; 1.0738x over previous
#include <cuda_runtime.h>
#include <cuda_fp16.h>
#include <cuda_bf16.h>
#include <cstdint>

// Problem dims (fixed by dataset)
#define BB 4
#define TT_ 512
#define UU 128
#define DD 512
#define VV 512
#define MS (BB * TT_)    // 2048 speech rows
#define MT (BB * UU)     // 512 text rows
#define MA (MS + MT)     // 2560 combined A rows

// Scratch
__device__ float g_sp[MS * VV];   // speech @ W^T          (4 MB)
__device__ float g_tp[MT * VV];   // text @ W^T + bias     (1 MB)
__device__ __align__(16) __half g_Ah[MA * DD];   // fp16(A)
__device__ __align__(16) __half g_Wh[VV * DD];   // fp16(W * 2^9) hi
__device__ __align__(16) __half g_Wl[VV * DD];   // fp16 residual of W * 2^9

#define WSCALE 512.0f
#define WINV   0.001953125f   // 2^-9 exact

__device__ __forceinline__ uint32_t s2u(const void* p) {
    return (uint32_t)__cvta_generic_to_shared(p);
}

#define LDSM4(r0, r1, r2, r3, addr) \
    asm volatile("ldmatrix.sync.aligned.m8n8.x4.shared.b16 {%0,%1,%2,%3}, [%4];" \
                 : "=r"(r0), "=r"(r1), "=r"(r2), "=r"(r3) : "r"(addr))
#define MMA16816F16(d, a0, a1, a2, a3, b0, b1) \
    asm volatile("mma.sync.aligned.m16n8k16.row.col.f32.f16.f16.f32 " \
                 "{%0,%1,%2,%3},{%4,%5,%6,%7},{%8,%9},{%0,%1,%2,%3};" \
                 : "+f"(d[0]), "+f"(d[1]), "+f"(d[2]), "+f"(d[3]) \
                 : "r"(a0), "r"(a1), "r"(a2), "r"(a3), "r"(b0), "r"(b1))
#define CP16(saddr, gptr) \
    asm volatile("cp.async.cg.shared.global [%0], [%1], 16;" \
                 :: "r"(saddr), "l"(gptr))
#define CP_COMMIT() asm volatile("cp.async.commit_group;")
#define CP_WAIT1()  asm volatile("cp.async.wait_group 1;")
#define CP_WAIT0()  asm volatile("cp.async.wait_group 0;")

// ---------------------------------------------------------------------------
// Kernel 0: convert.  A -> fp16 hi only.  W -> (fp16 hi, fp16 lo) of W*2^9.
// 768 blocks x 256 threads x 8 elems = 1,572,864 elements exactly.
// Also writes the float-cast length tail.
// ---------------------------------------------------------------------------
__global__ __launch_bounds__(256)
void convert_kernel(const float* __restrict__ speech,
                    const float* __restrict__ text,
                    const float* __restrict__ Wm,
                    const int* __restrict__ slen,
                    const int* __restrict__ tlen,
                    float* __restrict__ out)
{
    const size_t e = ((size_t)blockIdx.x * 256 + threadIdx.x) * 8;

    if (e < (size_t)MA * DD) {
        // A part: single fp16 output
        const float* src = (e < (size_t)MS * DD)
                         ? speech + e
                         : text + (e - (size_t)MS * DD);
        float4 x0 = *(const float4*)src;
        float4 x1 = *(const float4*)(src + 4);
        float xs[8] = {x0.x, x0.y, x0.z, x0.w, x1.x, x1.y, x1.z, x1.w};
        union { __half h[8]; uint4 v; } uh;
#pragma unroll
        for (int i = 0; i < 8; i++) uh.h[i] = __float2half_rn(xs[i]);
        *(uint4*)(g_Ah + e) = uh.v;
    } else {
        // W part: hi/lo split of W * 2^9
        size_t w = e - (size_t)MA * DD;
        const float* src = Wm + w;
        float4 x0 = *(const float4*)src;
        float4 x1 = *(const float4*)(src + 4);
        float xs[8] = {x0.x, x0.y, x0.z, x0.w, x1.x, x1.y, x1.z, x1.w};
        union { __half h[8]; uint4 v; } uhi, ulo;
#pragma unroll
        for (int i = 0; i < 8; i++) {
            float xw = xs[i] * WSCALE;
            __half h = __float2half_rn(xw);
            uhi.h[i] = h;
            ulo.h[i] = __float2half_rn(xw - __half2float(h));
        }
        *(uint4*)(g_Wh + w) = uhi.v;
        *(uint4*)(g_Wl + w) = ulo.v;
    }

    // Length tail: outputs 1 and 2 flattened after logits, as float32.
    if (blockIdx.x == 0 && threadIdx.x < 8) {
        size_t base = (size_t)BB * TT_ * UU * VV;
        int i = threadIdx.x;
        if (i < 4) out[base + i] = (float)slen[i];
        else       out[base + i] = (float)tlen[i - 4];
    }
}

// ---------------------------------------------------------------------------
// Kernel 1: tensor-core 2-term fp16 GEMM, 3-stage cp.async pipeline.
// C = (Ah*Wh + Ah*Wl) * 2^-9  (+bias for text)   [drops Al*Wh ~ 1.7e-4 rel]
// 64x64 tiles, 256 threads (8 warps = 4m x 2n of m16n32), grid 320
// (rb>=32 -> text). Stages: {Ah | Wh | Wl} 5120B each, 15360B/stage.
// ---------------------------------------------------------------------------
__global__ __launch_bounds__(256, 3)
void mma_gemm_kernel(const float* __restrict__ bias)
{
    __shared__ __align__(16) unsigned char smem[3][15360];

    const int t   = blockIdx.x;     // 0..319
    const int tid = threadIdx.x;
    const int rb  = t >> 3;         // 0..39 (combined row-block)
    const int v0  = (t & 7) * 64;
    const bool is_text = (rb >= 32);
    const int m0 = rb * 64;
    float* C = is_text ? g_tp + (size_t)(rb - 32) * 64 * VV
                       : g_sp + (size_t)rb * 64 * VV;

    // gmem->smem loaders: row ar (0..63), 16B segment ac (0..3)
    const int ar = tid >> 2, ac = tid & 3;
    const __half* pAh = g_Ah + (size_t)(m0 + ar) * DD + ac * 8;
    const __half* pWh = g_Wh + (size_t)(v0 + ar) * DD + ac * 8;
    const __half* pWl = g_Wl + (size_t)(v0 + ar) * DD + ac * 8;
    const int soff = ar * 80 + ac * 16;

    // warp tile coords: 4m x 2n grid of m16 x n32 warp tiles
    const int lane = tid & 31;
    const int wrp  = tid >> 5;
    const int wm   = wrp & 3;       // m16 group (0..3)
    const int wn   = wrp >> 2;      // n32 group (0..1)

    const int aRow  = wm * 16 + (lane & 15);
    const int aByte = ((lane >> 4) & 1) * 16;
    // B LDSM4 packing: (j-pair, k-half) quads
    const int bRow4  = wn * 32 + ((lane >> 4) & 1) * 8 + (lane & 7);
    const int bByte4 = ((lane >> 3) & 1) * 16;

    float acc[4][4];
#pragma unroll
    for (int j = 0; j < 4; j++)
#pragma unroll
        for (int i = 0; i < 4; i++) acc[j][i] = 0.f;

    // cp.async issue of chunk kc into stage s
    auto issue = [&](int kc, int s) {
        unsigned char* nb = smem[s];
        const int ko = kc * 32;     // 32 fp16 per chunk per row
        CP16(s2u(nb +         soff), pAh + ko);
        CP16(s2u(nb +  5120 + soff), pWh + ko);
        CP16(s2u(nb + 10240 + soff), pWl + ko);
        CP_COMMIT();
    };

    issue(0, 0);
    issue(1, 1);

    int sbuf = 0;
    for (int kc = 0; kc < 16; kc++) {
        if (kc == 15) { CP_WAIT0(); } else { CP_WAIT1(); }
        __syncthreads();

        if (kc < 14) {
            int ns = sbuf + 2; if (ns >= 3) ns -= 3;
            issue(kc + 2, ns);
        }

        unsigned char* cb = smem[sbuf];
#pragma unroll
        for (int ks = 0; ks < 2; ks++) {
            uint32_t aAddr = s2u(cb + aRow * 80 + ks * 32 + aByte);
            uint32_t a0, a1, a2, a3;
            LDSM4(a0, a1, a2, a3, aAddr);

            uint32_t bAddrBase = s2u(cb + 5120 + bRow4 * 80 + ks * 32 + bByte4);
            uint32_t bh[8], bl[8];
#pragma unroll
            for (int jp = 0; jp < 2; jp++) {
                uint32_t ba = bAddrBase + jp * (16 * 80);
                LDSM4(bh[jp*4+0], bh[jp*4+1], bh[jp*4+2], bh[jp*4+3], ba);
                LDSM4(bl[jp*4+0], bl[jp*4+1], bl[jp*4+2], bl[jp*4+3], ba + 5120);
            }
#pragma unroll
            for (int j = 0; j < 4; j++) {
                MMA16816F16(acc[j], a0, a1, a2, a3, bh[j*2], bh[j*2+1]);
                MMA16816F16(acc[j], a0, a1, a2, a3, bl[j*2], bl[j*2+1]);
            }
        }
        __syncthreads();
        if (++sbuf == 3) sbuf = 0;
    }

    // Epilogue: unscale by 2^-9, add bias (text), store.
    const int erow  = wm * 16 + (lane >> 2);
    const int ecol0 = wn * 32 + (lane & 3) * 2;
#pragma unroll
    for (int j = 0; j < 4; j++) {
        const int col = ecol0 + j * 8;
        float b0v = 0.f, b1v = 0.f;
        if (is_text) { b0v = bias[v0 + col]; b1v = bias[v0 + col + 1]; }
        float2 o0 = make_float2(acc[j][0] * WINV + b0v, acc[j][1] * WINV + b1v);
        float2 o1 = make_float2(acc[j][2] * WINV + b0v, acc[j][3] * WINV + b1v);
        *(float2*)(C + (size_t)erow * VV + v0 + col)       = o0;
        *(float2*)(C + (size_t)(erow + 8) * VV + v0 + col) = o1;
    }
}

// ---------------------------------------------------------------------------
// Kernel 2: broadcast add: out[bt, u, v] = sp[bt, v] + tp[b*U + u, v].
// Exact best-measured config: one block per bt row, 128 threads, plain
// stores. 87.5 us — the HBM write floor.
// ---------------------------------------------------------------------------
__global__ __launch_bounds__(128)
void bcast_add_kernel(float* __restrict__ out)
{
    const int bt  = blockIdx.x;           // 0..2047
    const int b   = bt >> 9;              // bt / T
    const int tid = threadIdx.x;          // 0..127 -> v4 index

    const float4* sp4 = (const float4*)g_sp;
    const float4* tp4 = (const float4*)g_tp;

    float4 s = sp4[(size_t)bt * 128 + tid];

    const float4* tprow = tp4 + (size_t)b * UU * 128 + tid;
    float4* ob = (float4*)out + (size_t)bt * UU * 128 + tid;

#pragma unroll 4
    for (int u = 0; u < UU; u++) {
        float4 t = tprow[(size_t)u * 128];
        float4 r;
        r.x = s.x + t.x;
        r.y = s.y + t.y;
        r.z = s.z + t.z;
        r.w = s.w + t.w;
        ob[(size_t)u * 128] = r;
    }
}

extern "C" void kernel_launch(void* const* d_in, const int* in_sizes, int n_in,
                              void* d_out, int out_size)
{
    const float* speech = (const float*)d_in[0];
    const float* text   = (const float*)d_in[1];
    const float* Wm     = (const float*)d_in[2];
    const float* bias   = (const float*)d_in[3];
    const int*   slen   = (const int*)d_in[4];
    const int*   tlen   = (const int*)d_in[5];

    // Phase 0: fp16 conversion (+ length tail)
    convert_kernel<<<768, 256>>>(speech, text, Wm, slen, tlen, (float*)d_out);

    // Phase 1: tensor-core 2-term fp16 GEMM (speech + text w/ bias)
    mma_gemm_kernel<<<320, 256>>>(bias);

    // Phase 2: broadcast add (DRAM-write-bound floor)
    bcast_add_kernel<<<MS, 128>>>((float*)d_out);
}